// round 14
// baseline (speedup 1.0000x reference)
#include <cuda_runtime.h>
#include <cuda_bf16.h>

#define HW     8192
#define THRESH 0.5f
#define TX     128      // output tile cols per block
#define TY     64       // output tile rows per block
#define IN_H   72       // h rows per tile (TY + 8 halo)
#define H_PAD  128      // h_s row stride (row-major, conflict-free both phases)
#define NTHREADS 256

#define SMEM_BYTES (IN_H * H_PAD * (int)sizeof(float))   // 36864 B

// Raw-domain trick: thresh(x) = x*[x>0.5] is monotone, so
// maxpool(thresh(X)) == thresh(maxpool(X)) and the peak test becomes
//   conf = mpraw  iff  mpraw > 0.5  &&  mpraw == ctr_raw
// on RAW values (inputs are >= 0; zero-padding at borders is safe).
// Phase A encodes (hraw == ctr_raw) into the sign bit of hraw.

template<bool EDGE>
__device__ __forceinline__ void phaseA(const float* __restrict__ in,
                                       float* __restrict__ h_s,
                                       int gr0, int cb0, int warp, int lane, int bx)
{
    const float4 z = make_float4(0.f, 0.f, 0.f, 0.f);
    const bool lok = !EDGE || !(bx == 0 && lane == 0);
    const bool rok = !EDGE || !(bx == 63 && lane == 31);
    const int  lofs = (EDGE && !lok) ? 0 : (4 * lane - 4);
    const int  rofs = (EDGE && !rok) ? (4 * lane) : (4 * lane + 4);

    // Double-buffer V only (keeps live regs ~48 so 5 CTAs/SM fit).
    // L/R hit the same 128B lines as neighboring lanes' V -> L1/MSHR merge.
    float4 V, nV;
    {
        const int gr = gr0 + warp;
        V = ((unsigned)gr < (unsigned)HW)
          ? *reinterpret_cast<const float4*>(in + (size_t)gr * HW + cb0 + 4 * lane)
          : z;
    }
#pragma unroll
    for (int it = 0; it < 9; it++) {            // 72 rows / 8 warps
        const int gr  = gr0 + warp + 8 * it;
        const bool rin = (unsigned)gr < (unsigned)HW;   // warp-uniform
        // issue halo loads for current row first
        float4 L = z, R = z;
        if (rin) {
            const float* rp = in + (size_t)gr * HW + cb0;
            if (!EDGE || lok) L = *reinterpret_cast<const float4*>(&rp[lofs]);
            if (!EDGE || rok) R = *reinterpret_cast<const float4*>(&rp[rofs]);
        }
        // prefetch next row's V
        if (it < 8) {
            const int ngr = gr + 8;
            nV = ((unsigned)ngr < (unsigned)HW)
               ? *reinterpret_cast<const float4*>(in + (size_t)ngr * HW + cb0 + 4 * lane)
               : z;
        }
        // horizontal 9-max on RAW values from L | V | R
        const float s3 = L.w;
        const float s2 = fmaxf(L.z, s3);
        const float s1 = fmaxf(L.y, s2);
        const float s0 = fmaxf(L.x, s1);
        const float M  = fmaxf(fmaxf(V.x, V.y), fmaxf(V.z, V.w));
        const float p0 = R.x;
        const float p1 = fmaxf(p0, R.y);
        const float p2 = fmaxf(p1, R.z);
        const float p3 = fmaxf(p2, R.w);
        const float hx = fmaxf(fmaxf(s0, M), p0);
        const float hy = fmaxf(fmaxf(s1, M), p1);
        const float hz = fmaxf(fmaxf(s2, M), p2);
        const float hw = fmaxf(fmaxf(s3, M), p3);
        float4 o;   // sign bit = (h == center): h >= 0 so -h / -0.0 carries it
        o.x = (hx == V.x) ? -hx : hx;
        o.y = (hy == V.y) ? -hy : hy;
        o.z = (hz == V.z) ? -hz : hz;
        o.w = (hw == V.w) ? -hw : hw;
        const int row = warp + 8 * it;
        *reinterpret_cast<float4*>(&h_s[row * H_PAD + 4 * lane]) = o;
        V = nV;
    }
}

__global__ void __launch_bounds__(NTHREADS, 5)
postprocess_kernel(const float* __restrict__ in, float* __restrict__ out)
{
    extern __shared__ float h_s[];      // [IN_H][H_PAD] row-major

    const int bx = blockIdx.x;          // 0..63
    const int by = blockIdx.y;          // 0..127
    const int tid  = threadIdx.x;
    const int warp = tid >> 5;          // 0..7
    const int lane = tid & 31;

    const int gr0 = by * TY - 4;        // first h row in global coords
    const int cb0 = bx * TX;            // first output col of tile

    // -------- Phase A: one warp per row; 3 coalesced LDGs, V double-buffered
    if (bx > 0 && bx < 63)
        phaseA<false>(in, h_s, gr0, cb0, warp, lane, bx);
    else
        phaseA<true>(in, h_s, gr0, cb0, warp, lane, bx);
    __syncthreads();

    // -------- Phase B: vertical 9-max, 1 col/thread, 32-row strips --------
    // 256 tasks: col 0..127 x strip 0..1. 5 blocks of 8 h rows (Gil-Werman):
    // reads 40 h rows per 32 outputs (amp 1.25x), conflict-free scalar LDS,
    // coalesced scalar STG down the column. fabs folds into FMNMX |R| mods.
    {
        const int c = tid & 127;            // local output col
        const int s = tid >> 7;             // strip 0/1
        const int r0 = s * 32;
        const float* hp = &h_s[r0 * H_PAD + c];
        float* op = out + (size_t)(by * TY + r0) * HW + (size_t)(cb0 + c);

        float S[8], rawt[4], C[8];
        // Block 0 (h rows r0..r0+7): suffix maxes of |.|, keep raw tail
        {
#pragma unroll
            for (int j = 0; j < 8; j++) C[j] = hp[j * H_PAD];
#pragma unroll
            for (int k = 0; k < 4; k++) rawt[k] = C[4 + k];
            S[7] = fabsf(C[7]);
#pragma unroll
            for (int j = 6; j >= 0; j--) S[j] = fmaxf(fabsf(C[j]), S[j + 1]);
        }
        // Stream 4 blocks of 8, each emits 8 output rows
#pragma unroll
        for (int k = 1; k <= 4; k++) {
#pragma unroll
            for (int j = 0; j < 8; j++) C[j] = hp[(8 * k + j) * H_PAD];
            float P = fabsf(C[0]);
#pragma unroll
            for (int i = 0; i < 8; i++) {
                if (i > 0) P = fmaxf(P, fabsf(C[i]));
                const float mp = fmaxf(S[i], P);          // 9-tap vertical max
                const float cs = (i < 4) ? rawt[i] : C[i - 4];
                // peak iff mp == -cs (sign flag + magnitude match) and above thresh
                op[(size_t)(8 * (k - 1) + i) * HW] =
                    (mp == -cs && mp > THRESH) ? mp : 0.f;
            }
#pragma unroll
            for (int t = 0; t < 4; t++) rawt[t] = C[4 + t];
            S[7] = fabsf(C[7]);
#pragma unroll
            for (int j = 6; j >= 0; j--) S[j] = fmaxf(fabsf(C[j]), S[j + 1]);
        }
    }
}

extern "C" void kernel_launch(void* const* d_in, const int* in_sizes, int n_in,
                              void* d_out, int out_size)
{
    const float* in = (const float*)d_in[0];
    float* out = (float*)d_out;

    static bool attr_set = false;
    if (!attr_set) {
        cudaFuncSetAttribute(postprocess_kernel,
                             cudaFuncAttributeMaxDynamicSharedMemorySize,
                             SMEM_BYTES);
        attr_set = true;
    }

    dim3 grid(HW / TX, HW / TY);   // 64 x 128
    postprocess_kernel<<<grid, NTHREADS, SMEM_BYTES>>>(in, out);
}